// round 3
// baseline (speedup 1.0000x reference)
#include <cuda_runtime.h>
#include <cstdint>

// Problem constants
#define B_   4
#define L_   1024
#define H_   8
#define D_   512
#define DK_  64
#define HB_  32      // H*B

// ---------------- scratch (device globals; referenced directly from device
// code so the host never needs cudaGetSymbolAddress) ------------------------
__device__ __align__(256) float g_qhT[HB_ * DK_ * L_];   // [hb][dk][l]
__device__ __align__(256) float g_khT[HB_ * DK_ * L_];   // [hb][dk][l]
__device__ __align__(256) float g_vh [HB_ * L_ * DK_];   // [hb][l][dk]
__device__ __align__(256) float g_sh [HB_ * L_];         // [hb][l]
__device__ __align__(256) float g_om [B_ * L_ * D_];     // [b*l][d]
__device__ __align__(256) float g_wT [4][D_ * D_];       // WqT,WkT,WvT,WoT

// ---------------- 512x512 transpose (weights) -------------------------------
__global__ void transpose512(const float* __restrict__ A, int which) {
    __shared__ float t[32][33];
    float* AT = g_wT[which];
    int bx = blockIdx.x * 32, by = blockIdx.y * 32;
    int tx = threadIdx.x, ty0 = threadIdx.y;
    #pragma unroll
    for (int i = ty0; i < 32; i += 8)
        t[i][tx] = A[(size_t)(by + i) * 512 + bx + tx];
    __syncthreads();
    #pragma unroll
    for (int i = ty0; i < 32; i += 8)
        AT[(size_t)(bx + i) * 512 + by + tx] = t[tx][i];
}

// ---------------- sigma projection: g_sh[h*4+b][l] = (Sigma @ Ws^T) ---------
__global__ void sigma_proj(const float* __restrict__ Sigma,
                           const float* __restrict__ Ws) {
    int idx = blockIdx.x * 128 + threadIdx.x;   // 0..4095  (b*L + l)
    int b = idx >> 10, l = idx & 1023;
    float s[8];
    #pragma unroll
    for (int i = 0; i < 8; i++) s[i] = Sigma[idx * 8 + i];
    #pragma unroll
    for (int h = 0; h < 8; h++) {
        float a = 0.f;
        #pragma unroll
        for (int i = 0; i < 8; i++) a = fmaf(s[i], Ws[h * 8 + i], a);
        g_sh[(h * 4 + b) * 1024 + l] = a;
    }
}

// ---------------- generic [4096,512] @ WT, 4 variants -----------------------
// MODE 0: Q -> g_qhT [hb][dk][l]      (WT = g_wT[0])
// MODE 1: K -> g_khT [hb][dk][l]      (WT = g_wT[1])
// MODE 2: V -> g_vh  [hb][l][dk]      (WT = g_wT[2])
// MODE 3: g_om -> dst plain [row][col](WT = g_wT[3])
template <int MODE>
__global__ __launch_bounds__(256)
void gemm512(const float* __restrict__ Xin, float* __restrict__ dstf) {
    __shared__ float As[64][33];
    __shared__ float Bs[32][64];
    const float* X  = (MODE == 3) ? g_om : Xin;
    const float* WT = g_wT[MODE];
    const int tid = threadIdx.x;
    const int m0 = blockIdx.y * 64, n0 = blockIdx.x * 64;
    const int ty = tid >> 4, tx = tid & 15;
    float acc[4][4] = {};

    for (int k0 = 0; k0 < 512; k0 += 32) {
        #pragma unroll
        for (int i = 0; i < 2; i++) {
            int e = tid + 256 * i;           // 512 float4 of A (64x32)
            int row = e >> 3, k4 = e & 7;
            float4 v = *(const float4*)(X + (size_t)(m0 + row) * 512 + k0 + k4 * 4);
            As[row][k4 * 4 + 0] = v.x; As[row][k4 * 4 + 1] = v.y;
            As[row][k4 * 4 + 2] = v.z; As[row][k4 * 4 + 3] = v.w;
        }
        #pragma unroll
        for (int i = 0; i < 2; i++) {
            int e = tid + 256 * i;           // 512 float4 of B (32x64), WT is [k][n]
            int n4 = e & 15, kk = e >> 4;
            *(float4*)&Bs[kk][n4 * 4] =
                *(const float4*)(WT + (size_t)(k0 + kk) * 512 + n0 + n4 * 4);
        }
        __syncthreads();
        #pragma unroll 8
        for (int kk = 0; kk < 32; kk++) {
            float4 b4 = *(const float4*)&Bs[kk][tx * 4];
            #pragma unroll
            for (int i = 0; i < 4; i++) {
                float a = As[ty * 4 + i][kk];
                acc[i][0] = fmaf(a, b4.x, acc[i][0]);
                acc[i][1] = fmaf(a, b4.y, acc[i][1]);
                acc[i][2] = fmaf(a, b4.z, acc[i][2]);
                acc[i][3] = fmaf(a, b4.w, acc[i][3]);
            }
        }
        __syncthreads();
    }

    const int h  = n0 >> 6;        // N tile == one head (BN=64=DK)
    const int b  = m0 >> 10;       // M tile stays within one batch
    const int l0 = m0 & 1023;

    if constexpr (MODE == 3) {
        #pragma unroll
        for (int i = 0; i < 4; i++) {
            float4 v = make_float4(acc[i][0], acc[i][1], acc[i][2], acc[i][3]);
            *(float4*)(dstf + (size_t)(m0 + ty * 4 + i) * 512 + n0 + tx * 4) = v;
        }
    } else if constexpr (MODE == 2) {
        #pragma unroll
        for (int i = 0; i < 4; i++) {
            float4 v = make_float4(acc[i][0], acc[i][1], acc[i][2], acc[i][3]);
            *(float4*)(g_vh + ((size_t)((h * 4 + b) * 1024 + l0 + ty * 4 + i)) * 64 + tx * 4) = v;
        }
    } else {
        float* dst = (MODE == 0) ? g_qhT : g_khT;
        __shared__ float Cs[64][65];
        #pragma unroll
        for (int i = 0; i < 4; i++)
            #pragma unroll
            for (int j = 0; j < 4; j++)
                Cs[tx * 4 + j][ty * 4 + i] = acc[i][j];
        __syncthreads();
        #pragma unroll
        for (int i = 0; i < 16; i++) {
            int e = tid + 256 * i;           // 4096 scalars, coalesced along l
            int l = e & 63, n = e >> 6;
            dst[((size_t)((h * 4 + b) * 64 + n)) * 1024 + l0 + l] = Cs[n][l];
        }
    }
}

// ---------------- Gaussian prior: softmax over -(i-j)^2/(2 s^2) -------------
__global__ __launch_bounds__(256)
void prior_kernel(float* __restrict__ prior) {
    const int i  = blockIdx.x;
    const int hb = blockIdx.y;
    const int t  = threadIdx.x;
    const int lane = t & 31, w = t >> 5;
    float s = 0.f;
    if (lane == 0) s = g_sh[hb * 1024 + i];
    s = __shfl_sync(0xffffffffu, s, 0);
    float c = -0.5f / (s * s);
    float ev[4];
    float lsum = 0.f;
    #pragma unroll
    for (int k = 0; k < 4; k++) {
        int j = t + 256 * k;
        int d = i - j;
        float e = d ? __expf((float)(d * d) * c) : 1.0f;
        ev[k] = e;
        lsum += e;
    }
    __shared__ float wsum[8];
    #pragma unroll
    for (int o = 16; o; o >>= 1) lsum += __shfl_xor_sync(0xffffffffu, lsum, o);
    if (lane == 0) wsum[w] = lsum;
    __syncthreads();
    float tot = wsum[0] + wsum[1] + wsum[2] + wsum[3] + wsum[4] + wsum[5] + wsum[6] + wsum[7];
    float rinv = 1.0f / tot;
    float* row = prior + ((size_t)(hb * 1024 + i)) * 1024;
    #pragma unroll
    for (int k = 0; k < 4; k++) row[t + 256 * k] = ev[k] * rinv;
}

// ---------------- scores + fused softmax -> series --------------------------
__global__ __launch_bounds__(256)
void scores_kernel(float* __restrict__ series) {
    extern __shared__ float sm[];
    float* Ssm = sm;                 // [32][1024]
    float* Qs  = sm + 32768;         // [64][32]
    float* Ks  = sm + 32768 + 2048;  // [64][128]

    const int tid = threadIdx.x;
    const int hb  = blockIdx.y;
    const int r0  = blockIdx.x * 32;
    const float* Qb = g_qhT + (size_t)hb * 64 * 1024;
    const float* Kb = g_khT + (size_t)hb * 64 * 1024;

    // Q tile [k][r] : 64x32
    #pragma unroll
    for (int i = 0; i < 2; i++) {
        int e = tid + 256 * i;       // 512 float4
        int r4 = e & 7, k = e >> 3;
        *(float4*)&Qs[k * 32 + r4 * 4] = *(const float4*)&Qb[(size_t)k * 1024 + r0 + r4 * 4];
    }

    const int ty = tid >> 5, tx = tid & 31;  // 8 row-groups x 32 col-groups
    const float scale = 0.125f;              // 1/sqrt(64)

    for (int kt = 0; kt < 8; kt++) {
        #pragma unroll
        for (int i = 0; i < 8; i++) {
            int e = tid + 256 * i;   // 2048 float4: K tile [k][c] 64x128
            int c4 = e & 31, k = e >> 5;
            *(float4*)&Ks[k * 128 + c4 * 4] =
                *(const float4*)&Kb[(size_t)k * 1024 + kt * 128 + c4 * 4];
        }
        __syncthreads();
        float acc[4][4] = {};
        #pragma unroll 8
        for (int kk = 0; kk < 64; kk++) {
            float4 a4 = *(const float4*)&Qs[kk * 32 + ty * 4];
            float4 b4 = *(const float4*)&Ks[kk * 128 + tx * 4];
            acc[0][0] = fmaf(a4.x, b4.x, acc[0][0]); acc[0][1] = fmaf(a4.x, b4.y, acc[0][1]);
            acc[0][2] = fmaf(a4.x, b4.z, acc[0][2]); acc[0][3] = fmaf(a4.x, b4.w, acc[0][3]);
            acc[1][0] = fmaf(a4.y, b4.x, acc[1][0]); acc[1][1] = fmaf(a4.y, b4.y, acc[1][1]);
            acc[1][2] = fmaf(a4.y, b4.z, acc[1][2]); acc[1][3] = fmaf(a4.y, b4.w, acc[1][3]);
            acc[2][0] = fmaf(a4.z, b4.x, acc[2][0]); acc[2][1] = fmaf(a4.z, b4.y, acc[2][1]);
            acc[2][2] = fmaf(a4.z, b4.z, acc[2][2]); acc[2][3] = fmaf(a4.z, b4.w, acc[2][3]);
            acc[3][0] = fmaf(a4.w, b4.x, acc[3][0]); acc[3][1] = fmaf(a4.w, b4.y, acc[3][1]);
            acc[3][2] = fmaf(a4.w, b4.z, acc[3][2]); acc[3][3] = fmaf(a4.w, b4.w, acc[3][3]);
        }
        #pragma unroll
        for (int i = 0; i < 4; i++) {
            float4 v = make_float4(acc[i][0] * scale, acc[i][1] * scale,
                                   acc[i][2] * scale, acc[i][3] * scale);
            *(float4*)&Ssm[(ty * 4 + i) * 1024 + kt * 128 + tx * 4] = v;
        }
        __syncthreads();
    }

    // fused softmax: warp w owns rows w*4 .. w*4+3
    const int w = tid >> 5, lane = tid & 31;
    for (int rr = 0; rr < 4; rr++) {
        int r = w * 4 + rr;
        float* row = Ssm + r * 1024;
        float m = -1e30f;
        for (int j = lane; j < 1024; j += 32) m = fmaxf(m, row[j]);
        #pragma unroll
        for (int o = 16; o; o >>= 1) m = fmaxf(m, __shfl_xor_sync(0xffffffffu, m, o));
        float sum = 0.f;
        for (int j = lane; j < 1024; j += 32) {
            float e = __expf(row[j] - m);
            row[j] = e;
            sum += e;
        }
        #pragma unroll
        for (int o = 16; o; o >>= 1) sum += __shfl_xor_sync(0xffffffffu, sum, o);
        float rinv = 1.0f / sum;
        float* grow = series + ((size_t)(hb * 1024 + r0 + r)) * 1024;
        for (int j = lane; j < 1024; j += 32) grow[j] = row[j] * rinv;
    }
}

// ---------------- O = series @ g_vh  ->  merged-head layout g_om ------------
__global__ __launch_bounds__(256)
void pv_gemm(const float* __restrict__ P) {
    __shared__ float As[128][33];
    __shared__ float Bs[32][64];
    const int hb = blockIdx.y;
    const int r0 = blockIdx.x * 128;
    const int tid = threadIdx.x;
    const int ty = tid >> 4, tx = tid & 15;
    const float* Pb = P + (size_t)hb * 1024 * 1024;
    const float* Vb = g_vh + (size_t)hb * 1024 * 64;
    float acc[8][4] = {};

    for (int k0 = 0; k0 < 1024; k0 += 32) {
        #pragma unroll
        for (int i = 0; i < 4; i++) {
            int e = tid + 256 * i;     // 1024 float4: P tile 128x32
            int row = e >> 3, k4 = e & 7;
            float4 v = *(const float4*)&Pb[(size_t)(r0 + row) * 1024 + k0 + k4 * 4];
            As[row][k4 * 4 + 0] = v.x; As[row][k4 * 4 + 1] = v.y;
            As[row][k4 * 4 + 2] = v.z; As[row][k4 * 4 + 3] = v.w;
        }
        #pragma unroll
        for (int i = 0; i < 2; i++) {
            int e = tid + 256 * i;     // 512 float4: V tile 32x64, already [k][n]
            int n4 = e & 15, kk = e >> 4;
            *(float4*)&Bs[kk][n4 * 4] = *(const float4*)&Vb[(size_t)(k0 + kk) * 64 + n4 * 4];
        }
        __syncthreads();
        #pragma unroll 8
        for (int kk = 0; kk < 32; kk++) {
            float4 b4 = *(const float4*)&Bs[kk][tx * 4];
            #pragma unroll
            for (int i = 0; i < 8; i++) {
                float a = As[ty * 8 + i][kk];
                acc[i][0] = fmaf(a, b4.x, acc[i][0]);
                acc[i][1] = fmaf(a, b4.y, acc[i][1]);
                acc[i][2] = fmaf(a, b4.z, acc[i][2]);
                acc[i][3] = fmaf(a, b4.w, acc[i][3]);
            }
        }
        __syncthreads();
    }
    const int h = hb >> 2, b = hb & 3;
    #pragma unroll
    for (int i = 0; i < 8; i++) {
        int l = r0 + ty * 8 + i;
        float4 v = make_float4(acc[i][0], acc[i][1], acc[i][2], acc[i][3]);
        *(float4*)(g_om + ((size_t)(b * 1024 + l)) * 512 + h * 64 + tx * 4) = v;
    }
}

// ---------------- launcher ---------------------------------------------------
extern "C" void kernel_launch(void* const* d_in, const int* in_sizes, int n_in,
                              void* d_out, int out_size) {
    const float* Sigma = (const float*)d_in[0];
    const float* Q     = (const float*)d_in[1];
    const float* K     = (const float*)d_in[2];
    const float* V     = (const float*)d_in[3];
    const float* Ws    = (const float*)d_in[4];
    const float* Wq    = (const float*)d_in[5];
    const float* Wk    = (const float*)d_in[6];
    const float* Wv    = (const float*)d_in[7];
    const float* Wo    = (const float*)d_in[8];

    float* out    = (float*)d_out;
    float* prior  = out;                      // 32*1024*1024
    float* series = out + 33554432;           // 32*1024*1024
    float* final_ = out + 67108864;           // 4*1024*512

    const int SMEM_SCORES = (32768 + 2048 + 8192) * 4;  // 172032 B
    static bool attr_done = false;
    if (!attr_done) {
        cudaFuncSetAttribute(scores_kernel,
                             cudaFuncAttributeMaxDynamicSharedMemorySize, SMEM_SCORES);
        attr_done = true;
    }

    dim3 tb(32, 8);
    dim3 tg(16, 16);
    transpose512<<<tg, tb>>>(Wq, 0);
    transpose512<<<tg, tb>>>(Wk, 1);
    transpose512<<<tg, tb>>>(Wv, 2);
    transpose512<<<tg, tb>>>(Wo, 3);

    sigma_proj<<<32, 128>>>(Sigma, Ws);

    dim3 gp(8, 64);
    gemm512<0><<<gp, 256>>>(Q, nullptr);
    gemm512<1><<<gp, 256>>>(K, nullptr);
    gemm512<2><<<gp, 256>>>(V, nullptr);

    prior_kernel<<<dim3(1024, 32), 256>>>(prior);

    scores_kernel<<<dim3(32, 32), 256, SMEM_SCORES>>>(series);

    pv_gemm<<<dim3(8, 32), 256>>>(series);

    gemm512<3><<<gp, 256>>>(nullptr, final_);
}

// round 7
// speedup vs baseline: 1.5150x; 1.5150x over previous
#include <cuda_runtime.h>
#include <cuda_bf16.h>
#include <cstdint>

#define HB_  32
#define L_   1024
#define DK_  64
#define D_   512
#define B_   4

// ---------------- device scratch --------------------------------------------
__device__ __align__(256) float g_sh [HB_ * L_];
__device__ __align__(256) float g_om [B_ * L_ * D_];
__device__ __align__(256) __nv_bfloat16 g_whi[4 * D_ * D_], g_wlo[4 * D_ * D_]; // [n][k] native
__device__ __align__(256) __nv_bfloat16 g_qhi[HB_*L_*DK_], g_qlo[HB_*L_*DK_];  // [hb][l][dk]
__device__ __align__(256) __nv_bfloat16 g_khi[HB_*L_*DK_], g_klo[HB_*L_*DK_];  // [hb][l][dk]
__device__ __align__(256) __nv_bfloat16 g_vhi[HB_*DK_*L_], g_vlo[HB_*DK_*L_];  // [hb][dk][l]

// ---------------- mma.sync / ldmatrix helpers --------------------------------
__device__ __forceinline__ uint32_t smem_u32(const void* p) {
    uint32_t a;
    asm("{ .reg .u64 t; cvta.to.shared.u64 t, %1; cvt.u32.u64 %0, t; }" : "=r"(a) : "l"(p));
    return a;
}
__device__ __forceinline__ void ldsm4(uint32_t& r0, uint32_t& r1, uint32_t& r2, uint32_t& r3,
                                      uint32_t a) {
    asm volatile("ldmatrix.sync.aligned.m8n8.x4.shared.b16 {%0,%1,%2,%3}, [%4];"
        : "=r"(r0), "=r"(r1), "=r"(r2), "=r"(r3) : "r"(a));
}
__device__ __forceinline__ void ldsm2(uint32_t& r0, uint32_t& r1, uint32_t a) {
    asm volatile("ldmatrix.sync.aligned.m8n8.x2.shared.b16 {%0,%1}, [%2];"
        : "=r"(r0), "=r"(r1) : "r"(a));
}
__device__ __forceinline__ void mma_bf16(float* c, const uint32_t* a, uint32_t b0, uint32_t b1) {
    asm volatile("mma.sync.aligned.m16n8k16.row.col.f32.bf16.bf16.f32 "
        "{%0,%1,%2,%3}, {%4,%5,%6,%7}, {%8,%9}, {%0,%1,%2,%3};"
        : "+f"(c[0]), "+f"(c[1]), "+f"(c[2]), "+f"(c[3])
        : "r"(a[0]), "r"(a[1]), "r"(a[2]), "r"(a[3]), "r"(b0), "r"(b1));
}
__device__ __forceinline__ uint32_t bfpair_hi(float a, float b) {
    return (uint32_t)__bfloat16_as_ushort(__float2bfloat16(a)) |
           ((uint32_t)__bfloat16_as_ushort(__float2bfloat16(b)) << 16);
}
__device__ __forceinline__ uint32_t bfpair_lo(float a, float b) {
    return bfpair_hi(a - __bfloat162float(__float2bfloat16(a)),
                     b - __bfloat162float(__float2bfloat16(b)));
}
__device__ __forceinline__ void pack8(const float* v, uint4& hi, uint4& lo) {
    hi = make_uint4(bfpair_hi(v[0],v[1]), bfpair_hi(v[2],v[3]),
                    bfpair_hi(v[4],v[5]), bfpair_hi(v[6],v[7]));
    lo = make_uint4(bfpair_lo(v[0],v[1]), bfpair_lo(v[2],v[3]),
                    bfpair_lo(v[4],v[5]), bfpair_lo(v[6],v[7]));
}
// padded bf16 smem rows: 64 elems + 8 pad = 144 bytes (conflict-free ldmatrix)
#define ROWB 144

// load 4 k-step A fragments (m16 rows at row0) from padded region
__device__ __forceinline__ void load_afrags(uint32_t base, int row0, int lane, uint32_t a[4][4]) {
    uint32_t r = base + (uint32_t)(row0 + (lane & 15)) * ROWB + ((lane >> 4) << 4);
    #pragma unroll
    for (int ks = 0; ks < 4; ks++) ldsm4(a[ks][0], a[ks][1], a[ks][2], a[ks][3], r + ks * 32);
}

// ---------------- weight split prep ------------------------------------------
__global__ void wsplit(const float* __restrict__ Wq, const float* __restrict__ Wk,
                       const float* __restrict__ Wv, const float* __restrict__ Wo) {
    int e = blockIdx.x * 256 + threadIdx.x;      // float4 index, 4*65536 total
    int w = e >> 16, idx = e & 65535;
    const float* W = (w == 0) ? Wq : (w == 1) ? Wk : (w == 2) ? Wv : Wo;
    float4 v = ((const float4*)W)[idx];
    ((uint2*)g_whi)[(size_t)w * 65536 + idx] = make_uint2(bfpair_hi(v.x,v.y), bfpair_hi(v.z,v.w));
    ((uint2*)g_wlo)[(size_t)w * 65536 + idx] = make_uint2(bfpair_lo(v.x,v.y), bfpair_lo(v.z,v.w));
}

// ---------------- sigma projection -------------------------------------------
__global__ void sigma_proj(const float* __restrict__ Sigma, const float* __restrict__ Ws) {
    int idx = blockIdx.x * 128 + threadIdx.x;
    int b = idx >> 10, l = idx & 1023;
    float s[8];
    #pragma unroll
    for (int i = 0; i < 8; i++) s[i] = Sigma[idx * 8 + i];
    #pragma unroll
    for (int h = 0; h < 8; h++) {
        float a = 0.f;
        #pragma unroll
        for (int i = 0; i < 8; i++) a = fmaf(s[i], Ws[h * 8 + i], a);
        g_sh[(h * 4 + b) * 1024 + l] = a;
    }
}

// ---------------- Gaussian prior ---------------------------------------------
__global__ __launch_bounds__(256)
void prior_kernel(float* __restrict__ prior) {
    const int i = blockIdx.x, hb = blockIdx.y, t = threadIdx.x;
    const int lane = t & 31, w = t >> 5;
    float s = 0.f;
    if (lane == 0) s = g_sh[hb * 1024 + i];
    s = __shfl_sync(0xffffffffu, s, 0);
    float c = -0.5f / (s * s);
    float ev[4], lsum = 0.f;
    #pragma unroll
    for (int k = 0; k < 4; k++) {
        int j = t + 256 * k, d = i - j;
        float e = d ? __expf((float)(d * d) * c) : 1.0f;
        ev[k] = e; lsum += e;
    }
    __shared__ float wsum[8];
    #pragma unroll
    for (int o = 16; o; o >>= 1) lsum += __shfl_xor_sync(0xffffffffu, lsum, o);
    if (lane == 0) wsum[w] = lsum;
    __syncthreads();
    float rinv = 1.0f / (wsum[0]+wsum[1]+wsum[2]+wsum[3]+wsum[4]+wsum[5]+wsum[6]+wsum[7]);
    float* row = prior + ((size_t)(hb * 1024 + i)) * 1024;
    #pragma unroll
    for (int k = 0; k < 4; k++) row[t + 256 * k] = ev[k] * rinv;
}

// ---------------- projection GEMM via mma.sync -------------------------------
// C[128x128] = X[m0..+128][512] @ W[n0..+128][512]^T, K-chunks of 64.
// MODE 0: Q->g_q{hi,lo}[hb][l][dk]  1: K  2: V->g_v{hi,lo}[hb][dk][l]  3: fp32 out
#define PJ_AHI 0
#define PJ_ALO 18432
#define PJ_BHI 36864
#define PJ_BLO 55296
#define PJ_ST  73728
#define PJ_SZ  141312
template <int MODE>
__global__ __launch_bounds__(256, 1)
void proj_mma(const float* __restrict__ Xin, float* __restrict__ dstf) {
    extern __shared__ char sm[];
    const uint32_t sb = smem_u32(sm);
    float* stg = (float*)(sm + PJ_ST);           // [128][132]
    const int tid = threadIdx.x, wid = tid >> 5, lane = tid & 31;
    const int m0 = blockIdx.x * 128, ny = blockIdx.y, n0 = ny * 128;
    const float* X = (MODE == 3) ? g_om : Xin;
    const int bI = m0 >> 10, l0 = m0 & 1023;

    float c[16][4];
    #pragma unroll
    for (int t2 = 0; t2 < 16; t2++) { c[t2][0]=c[t2][1]=c[t2][2]=c[t2][3]=0.f; }

    for (int kc = 0; kc < 8; kc++) {
        __syncthreads();
        // A: X fp32 -> split bf16 smem
        #pragma unroll
        for (int i = 0; i < 8; i++) {
            int e = tid + 256 * i, row = e >> 4, q = e & 15;
            float4 v = ((const float4*)X)[(size_t)(m0 + row) * 128 + kc * 16 + q];
            uint32_t off = (uint32_t)row * ROWB + q * 8;
            *(uint2*)(sm + PJ_AHI + off) = make_uint2(bfpair_hi(v.x,v.y), bfpair_hi(v.z,v.w));
            *(uint2*)(sm + PJ_ALO + off) = make_uint2(bfpair_lo(v.x,v.y), bfpair_lo(v.z,v.w));
        }
        // B: W bf16 native [n][k]
        #pragma unroll
        for (int i = 0; i < 4; i++) {
            int e = tid + 256 * i, row = e >> 3, q = e & 7;
            uint32_t off = (uint32_t)row * ROWB + q * 16;
            size_t gi = (size_t)MODE * 32768 + (size_t)(n0 + row) * 64 + kc * 8 + q;
            *(uint4*)(sm + PJ_BHI + off) = ((const uint4*)g_whi)[gi];
            *(uint4*)(sm + PJ_BLO + off) = ((const uint4*)g_wlo)[gi];
        }
        __syncthreads();
        uint32_t ah[4][4], al[4][4];
        load_afrags(sb + PJ_AHI, wid * 16, lane, ah);
        load_afrags(sb + PJ_ALO, wid * 16, lane, al);
        #pragma unroll
        for (int nt = 0; nt < 16; nt++) {
            uint32_t rb = sb + PJ_BHI + (uint32_t)(nt * 8 + (lane & 7)) * ROWB
                        + (((lane >> 3) & 1) << 4);
            #pragma unroll
            for (int ks = 0; ks < 4; ks++) {
                uint32_t bh0, bh1, bl0, bl1;
                ldsm2(bh0, bh1, rb + ks * 32);
                ldsm2(bl0, bl1, rb + (PJ_BLO - PJ_BHI) + ks * 32);
                mma_bf16(c[nt], ah[ks], bh0, bh1);
                mma_bf16(c[nt], ah[ks], bl0, bl1);
                mma_bf16(c[nt], al[ks], bh0, bh1);
            }
        }
    }
    // stage C
    __syncthreads();
    {
        int r = wid * 16 + (lane >> 2), col0 = (lane & 3) * 2;
        #pragma unroll
        for (int nt = 0; nt < 16; nt++) {
            *(float2*)&stg[r * 132 + nt * 8 + col0]       = make_float2(c[nt][0], c[nt][1]);
            *(float2*)&stg[(r + 8) * 132 + nt * 8 + col0] = make_float2(c[nt][2], c[nt][3]);
        }
    }
    __syncthreads();

    if constexpr (MODE == 3) {
        int r = tid >> 1, ch = (tid & 1) * 64;
        #pragma unroll
        for (int j = 0; j < 16; j++) {
            float4 v = *(float4*)&stg[r * 132 + ch + j * 4];
            *(float4*)(dstf + (size_t)(m0 + r) * 512 + n0 + ch + j * 4) = v;
        }
    } else if constexpr (MODE == 2) {
        // V -> [hb][dk][l]
        #pragma unroll
        for (int i = 0; i < 2; i++) {
            int e = tid + 256 * i;                 // (s,dk,lg): 2*64*4
            int s = e >> 8, rem = e & 255, dk = rem >> 2, lg = rem & 3;
            int hb = (2 * ny + s) * 4 + bI;
            #pragma unroll
            for (int j = 0; j < 4; j++) {
                float v[8];
                #pragma unroll
                for (int kk = 0; kk < 8; kk++)
                    v[kk] = stg[(lg * 32 + j * 8 + kk) * 132 + s * 64 + dk];
                uint4 hi, lo; pack8(v, hi, lo);
                size_t ui = (size_t)(hb * 64 + dk) * 128 + (l0 + lg * 32 + j * 8) / 8;
                ((uint4*)g_vhi)[ui] = hi;
                ((uint4*)g_vlo)[ui] = lo;
            }
        }
    } else {
        // Q/K -> [hb][l][dk]
        uint4* dhi = (uint4*)(MODE ? g_khi : g_qhi);
        uint4* dlo = (uint4*)(MODE ? g_klo : g_qlo);
        #pragma unroll
        for (int i = 0; i < 8; i++) {
            int e = tid + 256 * i;                 // 2048 uint4 = 2 heads * 128 rows * 8
            int s = e >> 10, rem = e & 1023, row = rem >> 3, q = rem & 7;
            int hb = (2 * ny + s) * 4 + bI;
            float v[8];
            #pragma unroll
            for (int kk = 0; kk < 8; kk++) v[kk] = stg[row * 132 + s * 64 + q * 8 + kk];
            uint4 hi, lo; pack8(v, hi, lo);
            size_t ui = (size_t)(hb * 1024 + l0 + row) * 8 + q;
            dhi[ui] = hi;
            dlo[ui] = lo;
        }
    }
}

// ---------------- scores + fused softmax -------------------------------------
#define SC_QHI 0
#define SC_QLO 18432
#define SC_KHI 36864
#define SC_KLO 55296
#define SC_ST  73728
#define SC_RS  141312
#define SC_SZ  141824
__global__ __launch_bounds__(256, 1)
void scores_mma(float* __restrict__ series) {
    extern __shared__ char sm[];
    const uint32_t sb = smem_u32(sm);
    float* stg = (float*)(sm + SC_ST);            // [128][132]
    float* rsm = (float*)(sm + SC_RS);            // [128]
    const int tid = threadIdx.x, wid = tid >> 5, lane = tid & 31;
    const int hb = blockIdx.y, r0 = blockIdx.x * 128;

    // Q block -> smem
    #pragma unroll
    for (int i = 0; i < 4; i++) {
        int e = tid + 256 * i, row = e >> 3, q = e & 7;
        uint32_t off = (uint32_t)row * ROWB + q * 16;
        size_t gi = (size_t)(hb * 1024 + r0 + row) * 8 + q;
        *(uint4*)(sm + SC_QHI + off) = ((const uint4*)g_qhi)[gi];
        *(uint4*)(sm + SC_QLO + off) = ((const uint4*)g_qlo)[gi];
    }
    __syncthreads();
    uint32_t ah[4][4], al[4][4];
    load_afrags(sb + SC_QHI, wid * 16, lane, ah);
    load_afrags(sb + SC_QLO, wid * 16, lane, al);

    float rs0 = 0.f, rs1 = 0.f;

    for (int ck = 0; ck < 8; ck++) {
        __syncthreads();
        #pragma unroll
        for (int i = 0; i < 4; i++) {
            int e = tid + 256 * i, row = e >> 3, q = e & 7;
            uint32_t off = (uint32_t)row * ROWB + q * 16;
            size_t gi = (size_t)(hb * 1024 + ck * 128 + row) * 8 + q;
            *(uint4*)(sm + SC_KHI + off) = ((const uint4*)g_khi)[gi];
            *(uint4*)(sm + SC_KLO + off) = ((const uint4*)g_klo)[gi];
        }
        __syncthreads();
        int r = wid * 16 + (lane >> 2), col0 = (lane & 3) * 2;
        #pragma unroll
        for (int nt = 0; nt < 16; nt++) {
            float c[4] = {0.f, 0.f, 0.f, 0.f};
            uint32_t rb = sb + SC_KHI + (uint32_t)(nt * 8 + (lane & 7)) * ROWB
                        + (((lane >> 3) & 1) << 4);
            #pragma unroll
            for (int ks = 0; ks < 4; ks++) {
                uint32_t bh0, bh1, bl0, bl1;
                ldsm2(bh0, bh1, rb + ks * 32);
                ldsm2(bl0, bl1, rb + (SC_KLO - SC_KHI) + ks * 32);
                mma_bf16(c, ah[ks], bh0, bh1);
                mma_bf16(c, ah[ks], bl0, bl1);
                mma_bf16(c, al[ks], bh0, bh1);
            }
            float e0 = __expf(0.125f * c[0]), e1 = __expf(0.125f * c[1]);
            float e2 = __expf(0.125f * c[2]), e3 = __expf(0.125f * c[3]);
            rs0 += e0 + e1; rs1 += e2 + e3;
            *(float2*)&stg[r * 132 + nt * 8 + col0]       = make_float2(e0, e1);
            *(float2*)&stg[(r + 8) * 132 + nt * 8 + col0] = make_float2(e2, e3);
        }
        __syncthreads();
        int rr = tid >> 1, ch = (tid & 1) * 64;
        float* grow = series + ((size_t)(hb * 1024 + r0 + rr)) * 1024 + ck * 128 + ch;
        #pragma unroll
        for (int j = 0; j < 16; j++)
            *(float4*)(grow + j * 4) = *(float4*)&stg[rr * 132 + ch + j * 4];
    }
    // rowsums
    rs0 += __shfl_xor_sync(0xffffffffu, rs0, 1); rs0 += __shfl_xor_sync(0xffffffffu, rs0, 2);
    rs1 += __shfl_xor_sync(0xffffffffu, rs1, 1); rs1 += __shfl_xor_sync(0xffffffffu, rs1, 2);
    if ((lane & 3) == 0) {
        rsm[wid * 16 + (lane >> 2)] = rs0;
        rsm[wid * 16 + (lane >> 2) + 8] = rs1;
    }
    __syncthreads();
    // normalize in place (L2-hot)
    {
        int r = tid >> 1;
        float ri = 1.0f / rsm[r];
        float4* row = (float4*)(series + ((size_t)(hb * 1024 + r0 + r)) * 1024) + (tid & 1) * 128;
        #pragma unroll 8
        for (int j = 0; j < 128; j++) {
            float4 v = row[j];
            v.x *= ri; v.y *= ri; v.z *= ri; v.w *= ri;
            row[j] = v;
        }
    }
}

// ---------------- O = series @ V ---------------------------------------------
#define PV_AHI 0
#define PV_ALO 18432
#define PV_BHI 36864
#define PV_BLO 46080
#define PV_ST  55296
#define PV_SZ  90112
__global__ __launch_bounds__(256, 1)
void pv_mma(const float* __restrict__ series) {
    extern __shared__ char sm[];
    const uint32_t sb = smem_u32(sm);
    float* stg = (float*)(sm + PV_ST);            // [128][68]
    const int tid = threadIdx.x, wid = tid >> 5, lane = tid & 31;
    const int hb = blockIdx.y, r0 = blockIdx.x * 128;

    float c[8][4];
    #pragma unroll
    for (int t2 = 0; t2 < 8; t2++) { c[t2][0]=c[t2][1]=c[t2][2]=c[t2][3]=0.f; }

    for (int kc = 0; kc < 16; kc++) {
        __syncthreads();
        #pragma unroll
        for (int i = 0; i < 8; i++) {
            int e = tid + 256 * i, row = e >> 4, q = e & 15;
            float4 v = ((const float4*)series)[(size_t)(hb * 1024 + r0 + row) * 256 + kc * 16 + q];
            uint32_t off = (uint32_t)row * ROWB + q * 8;
            *(uint2*)(sm + PV_AHI + off) = make_uint2(bfpair_hi(v.x,v.y), bfpair_hi(v.z,v.w));
            *(uint2*)(sm + PV_ALO + off) = make_uint2(bfpair_lo(v.x,v.y), bfpair_lo(v.z,v.w));
        }
        #pragma unroll
        for (int i = 0; i < 2; i++) {
            int e = tid + 256 * i, row = e >> 3, q = e & 7;
            uint32_t off = (uint32_t)row * ROWB + q * 16;
            size_t gi = (size_t)(hb * 64 + row) * 128 + kc * 8 + q;
            *(uint4*)(sm + PV_BHI + off) = ((const uint4*)g_vhi)[gi];
            *(uint4*)(sm + PV_BLO + off) = ((const uint4*)g_vlo)[gi];
        }
        __syncthreads();
        uint32_t ah[4][4], al[4][4];
        load_afrags(sb + PV_AHI, wid * 16, lane, ah);
        load_afrags(sb + PV_ALO, wid * 16, lane, al);
        #pragma unroll
        for (int nt = 0; nt < 8; nt++) {
            uint32_t rb = sb + PV_BHI + (uint32_t)(nt * 8 + (lane & 7)) * ROWB
                        + (((lane >> 3) & 1) << 4);
            #pragma unroll
            for (int ks = 0; ks < 4; ks++) {
                uint32_t bh0, bh1, bl0, bl1;
                ldsm2(bh0, bh1, rb + ks * 32);
                ldsm2(bl0, bl1, rb + (PV_BLO - PV_BHI) + ks * 32);
                mma_bf16(c[nt], ah[ks], bh0, bh1);
                mma_bf16(c[nt], ah[ks], bl0, bl1);
                mma_bf16(c[nt], al[ks], bh0, bh1);
            }
        }
    }
    __syncthreads();
    {
        int r = wid * 16 + (lane >> 2), col0 = (lane & 3) * 2;
        #pragma unroll
        for (int nt = 0; nt < 8; nt++) {
            *(float2*)&stg[r * 68 + nt * 8 + col0]       = make_float2(c[nt][0], c[nt][1]);
            *(float2*)&stg[(r + 8) * 68 + nt * 8 + col0] = make_float2(c[nt][2], c[nt][3]);
        }
    }
    __syncthreads();
    const int h = hb >> 2, b = hb & 3;
    int r = tid >> 1, ch = (tid & 1) * 32;
    #pragma unroll
    for (int j = 0; j < 8; j++) {
        float4 v = *(float4*)&stg[r * 68 + ch + j * 4];
        *(float4*)(g_om + (size_t)(b * 1024 + r0 + r) * 512 + h * 64 + ch + j * 4) = v;
    }
}

// ---------------- launcher ---------------------------------------------------
extern "C" void kernel_launch(void* const* d_in, const int* in_sizes, int n_in,
                              void* d_out, int out_size) {
    const float* Sigma = (const float*)d_in[0];
    const float* Q     = (const float*)d_in[1];
    const float* K     = (const float*)d_in[2];
    const float* V     = (const float*)d_in[3];
    const float* Ws    = (const float*)d_in[4];
    const float* Wq    = (const float*)d_in[5];
    const float* Wk    = (const float*)d_in[6];
    const float* Wv    = (const float*)d_in[7];
    const float* Wo    = (const float*)d_in[8];

    float* out    = (float*)d_out;
    float* prior  = out;
    float* series = out + 33554432;
    float* final_ = out + 67108864;

    static bool attr_done = false;
    if (!attr_done) {
        cudaFuncSetAttribute(proj_mma<0>, cudaFuncAttributeMaxDynamicSharedMemorySize, PJ_SZ);
        cudaFuncSetAttribute(proj_mma<1>, cudaFuncAttributeMaxDynamicSharedMemorySize, PJ_SZ);
        cudaFuncSetAttribute(proj_mma<2>, cudaFuncAttributeMaxDynamicSharedMemorySize, PJ_SZ);
        cudaFuncSetAttribute(proj_mma<3>, cudaFuncAttributeMaxDynamicSharedMemorySize, PJ_SZ);
        cudaFuncSetAttribute(scores_mma,  cudaFuncAttributeMaxDynamicSharedMemorySize, SC_SZ);
        cudaFuncSetAttribute(pv_mma,      cudaFuncAttributeMaxDynamicSharedMemorySize, PV_SZ);
        attr_done = true;
    }

    wsplit<<<1024, 256>>>(Wq, Wk, Wv, Wo);
    sigma_proj<<<32, 128>>>(Sigma, Ws);

    dim3 gpj(32, 4);
    proj_mma<0><<<gpj, 256, PJ_SZ>>>(Q, nullptr);
    proj_mma<1><<<gpj, 256, PJ_SZ>>>(K, nullptr);
    proj_mma<2><<<gpj, 256, PJ_SZ>>>(V, nullptr);

    prior_kernel<<<dim3(1024, 32), 256>>>(prior);

    scores_mma<<<dim3(8, 32), 256, SC_SZ>>>(series);
    pv_mma<<<dim3(8, 32), 256, PV_SZ>>>(series);

    proj_mma<3><<<gpj, 256, PJ_SZ>>>(nullptr, final_);
}

// round 8
// speedup vs baseline: 1.7965x; 1.1858x over previous
#include <cuda_runtime.h>
#include <cuda_bf16.h>
#include <cstdint>

#define HB_  32
#define L_   1024
#define DK_  64
#define D_   512
#define B_   4

// ---------------- device scratch --------------------------------------------
__device__ __align__(256) float g_sh [HB_ * L_];
__device__ __align__(256) float g_R  [HB_ * L_];       // softmax row sums
__device__ __align__(256) float g_om [B_ * L_ * D_];
__device__ __align__(256) __nv_bfloat16 g_whi[4 * D_ * D_], g_wlo[4 * D_ * D_]; // [n][k]
__device__ __align__(256) __nv_bfloat16 g_qhi[HB_*L_*DK_], g_qlo[HB_*L_*DK_];  // [hb][l][dk]
__device__ __align__(256) __nv_bfloat16 g_khi[HB_*L_*DK_], g_klo[HB_*L_*DK_];  // [hb][l][dk]
__device__ __align__(256) __nv_bfloat16 g_vhi[HB_*DK_*L_], g_vlo[HB_*DK_*L_];  // [hb][dk][l]
__device__ __align__(256) __nv_bfloat16 g_ehi[HB_*L_*L_], g_elo[HB_*L_*L_];    // unnormalized exp

// ---------------- mma.sync / ldmatrix helpers --------------------------------
__device__ __forceinline__ uint32_t smem_u32(const void* p) {
    uint32_t a;
    asm("{ .reg .u64 t; cvta.to.shared.u64 t, %1; cvt.u32.u64 %0, t; }" : "=r"(a) : "l"(p));
    return a;
}
__device__ __forceinline__ void ldsm4(uint32_t& r0, uint32_t& r1, uint32_t& r2, uint32_t& r3,
                                      uint32_t a) {
    asm volatile("ldmatrix.sync.aligned.m8n8.x4.shared.b16 {%0,%1,%2,%3}, [%4];"
        : "=r"(r0), "=r"(r1), "=r"(r2), "=r"(r3) : "r"(a));
}
__device__ __forceinline__ void ldsm2(uint32_t& r0, uint32_t& r1, uint32_t a) {
    asm volatile("ldmatrix.sync.aligned.m8n8.x2.shared.b16 {%0,%1}, [%2];"
        : "=r"(r0), "=r"(r1) : "r"(a));
}
__device__ __forceinline__ void mma_bf16(float* c, const uint32_t* a, uint32_t b0, uint32_t b1) {
    asm volatile("mma.sync.aligned.m16n8k16.row.col.f32.bf16.bf16.f32 "
        "{%0,%1,%2,%3}, {%4,%5,%6,%7}, {%8,%9}, {%0,%1,%2,%3};"
        : "+f"(c[0]), "+f"(c[1]), "+f"(c[2]), "+f"(c[3])
        : "r"(a[0]), "r"(a[1]), "r"(a[2]), "r"(a[3]), "r"(b0), "r"(b1));
}
__device__ __forceinline__ uint32_t bfpair_hi(float a, float b) {
    return (uint32_t)__bfloat16_as_ushort(__float2bfloat16(a)) |
           ((uint32_t)__bfloat16_as_ushort(__float2bfloat16(b)) << 16);
}
__device__ __forceinline__ uint32_t bfpair_lo(float a, float b) {
    return bfpair_hi(a - __bfloat162float(__float2bfloat16(a)),
                     b - __bfloat162float(__float2bfloat16(b)));
}
__device__ __forceinline__ void pack8(const float* v, uint4& hi, uint4& lo) {
    hi = make_uint4(bfpair_hi(v[0],v[1]), bfpair_hi(v[2],v[3]),
                    bfpair_hi(v[4],v[5]), bfpair_hi(v[6],v[7]));
    lo = make_uint4(bfpair_lo(v[0],v[1]), bfpair_lo(v[2],v[3]),
                    bfpair_lo(v[4],v[5]), bfpair_lo(v[6],v[7]));
}
// bf16 -> f32 (exact, bits<<16)
__device__ __forceinline__ float blo(uint32_t w) { return __uint_as_float(w << 16); }
__device__ __forceinline__ float bhi(uint32_t w) { return __uint_as_float(w & 0xFFFF0000u); }

#define ROWB 144   // padded bf16 smem row: 64 elems + 8 pad = 144 bytes

__device__ __forceinline__ void load_afrags(uint32_t base, int row0, int lane, uint32_t a[4][4]) {
    uint32_t r = base + (uint32_t)(row0 + (lane & 15)) * ROWB + ((lane >> 4) << 4);
    #pragma unroll
    for (int ks = 0; ks < 4; ks++) ldsm4(a[ks][0], a[ks][1], a[ks][2], a[ks][3], r + ks * 32);
}

// ---------------- weight split prep ------------------------------------------
__global__ void wsplit(const float* __restrict__ Wq, const float* __restrict__ Wk,
                       const float* __restrict__ Wv, const float* __restrict__ Wo) {
    int e = blockIdx.x * 256 + threadIdx.x;
    int w = e >> 16, idx = e & 65535;
    const float* W = (w == 0) ? Wq : (w == 1) ? Wk : (w == 2) ? Wv : Wo;
    float4 v = ((const float4*)W)[idx];
    ((uint2*)g_whi)[(size_t)w * 65536 + idx] = make_uint2(bfpair_hi(v.x,v.y), bfpair_hi(v.z,v.w));
    ((uint2*)g_wlo)[(size_t)w * 65536 + idx] = make_uint2(bfpair_lo(v.x,v.y), bfpair_lo(v.z,v.w));
}

// ---------------- sigma projection -------------------------------------------
__global__ void sigma_proj(const float* __restrict__ Sigma, const float* __restrict__ Ws) {
    int idx = blockIdx.x * 128 + threadIdx.x;
    int b = idx >> 10, l = idx & 1023;
    float s[8];
    #pragma unroll
    for (int i = 0; i < 8; i++) s[i] = Sigma[idx * 8 + i];
    #pragma unroll
    for (int h = 0; h < 8; h++) {
        float a = 0.f;
        #pragma unroll
        for (int i = 0; i < 8; i++) a = fmaf(s[i], Ws[h * 8 + i], a);
        g_sh[(h * 4 + b) * 1024 + l] = a;
    }
}

// ---------------- Gaussian prior ---------------------------------------------
__global__ __launch_bounds__(256)
void prior_kernel(float* __restrict__ prior) {
    const int i = blockIdx.x, hb = blockIdx.y, t = threadIdx.x;
    const int lane = t & 31, w = t >> 5;
    float s = 0.f;
    if (lane == 0) s = g_sh[hb * 1024 + i];
    s = __shfl_sync(0xffffffffu, s, 0);
    float c = -0.5f / (s * s);
    float ev[4], lsum = 0.f;
    #pragma unroll
    for (int k = 0; k < 4; k++) {
        int j = t + 256 * k, d = i - j;
        float e = d ? __expf((float)(d * d) * c) : 1.0f;
        ev[k] = e; lsum += e;
    }
    __shared__ float wsum[8];
    #pragma unroll
    for (int o = 16; o; o >>= 1) lsum += __shfl_xor_sync(0xffffffffu, lsum, o);
    if (lane == 0) wsum[w] = lsum;
    __syncthreads();
    float rinv = 1.0f / (wsum[0]+wsum[1]+wsum[2]+wsum[3]+wsum[4]+wsum[5]+wsum[6]+wsum[7]);
    float* row = prior + ((size_t)(hb * 1024 + i)) * 1024;
    #pragma unroll
    for (int k = 0; k < 4; k++) row[t + 256 * k] = ev[k] * rinv;
}

// ---------------- projection GEMM: M-tile 64, N-tile 128, warps 4x2 ----------
#define PJ_AHI 0
#define PJ_ALO 9216
#define PJ_BHI 18432
#define PJ_BLO 36864
#define PJ_ST  55296
#define PJ_SZ  89088
template <int MODE>
__global__ __launch_bounds__(256, 2)
void proj_mma(const float* __restrict__ Xin, float* __restrict__ dstf) {
    extern __shared__ char sm[];
    const uint32_t sb = smem_u32(sm);
    float* stg = (float*)(sm + PJ_ST);          // [64][132]
    const int tid = threadIdx.x, wid = tid >> 5, lane = tid & 31;
    const int wm = wid & 3, wn = wid >> 2;
    const int m0 = blockIdx.x * 64, ny = blockIdx.y, n0 = ny * 128;
    const float* X = (MODE == 3) ? g_om : Xin;
    const int bI = m0 >> 10, l0 = m0 & 1023;

    float c[8][4];
    #pragma unroll
    for (int t2 = 0; t2 < 8; t2++) { c[t2][0]=c[t2][1]=c[t2][2]=c[t2][3]=0.f; }

    for (int kc = 0; kc < 8; kc++) {
        __syncthreads();
        #pragma unroll
        for (int i = 0; i < 4; i++) {            // A: 64x64 f32 -> split bf16
            int e = tid + 256 * i, row = e >> 4, q = e & 15;
            float4 v = ((const float4*)X)[(size_t)(m0 + row) * 128 + kc * 16 + q];
            uint32_t off = (uint32_t)row * ROWB + q * 8;
            *(uint2*)(sm + PJ_AHI + off) = make_uint2(bfpair_hi(v.x,v.y), bfpair_hi(v.z,v.w));
            *(uint2*)(sm + PJ_ALO + off) = make_uint2(bfpair_lo(v.x,v.y), bfpair_lo(v.z,v.w));
        }
        #pragma unroll
        for (int i = 0; i < 4; i++) {            // B: W 128x64 bf16 native
            int e = tid + 256 * i, row = e >> 3, q = e & 7;
            uint32_t off = (uint32_t)row * ROWB + q * 16;
            size_t gi = (size_t)MODE * 32768 + (size_t)(n0 + row) * 64 + kc * 8 + q;
            *(uint4*)(sm + PJ_BHI + off) = ((const uint4*)g_whi)[gi];
            *(uint4*)(sm + PJ_BLO + off) = ((const uint4*)g_wlo)[gi];
        }
        __syncthreads();
        uint32_t ah[4][4], al[4][4];
        load_afrags(sb + PJ_AHI, wm * 16, lane, ah);
        load_afrags(sb + PJ_ALO, wm * 16, lane, al);
        #pragma unroll
        for (int nt = 0; nt < 8; nt++) {
            uint32_t rb = sb + PJ_BHI + (uint32_t)(wn * 64 + nt * 8 + (lane & 7)) * ROWB
                        + (((lane >> 3) & 1) << 4);
            #pragma unroll
            for (int ks = 0; ks < 4; ks++) {
                uint32_t bh0, bh1, bl0, bl1;
                ldsm2(bh0, bh1, rb + ks * 32);
                ldsm2(bl0, bl1, rb + (PJ_BLO - PJ_BHI) + ks * 32);
                mma_bf16(c[nt], ah[ks], bh0, bh1);
                mma_bf16(c[nt], ah[ks], bl0, bl1);
                mma_bf16(c[nt], al[ks], bh0, bh1);
            }
        }
    }
    __syncthreads();
    {
        int r = wm * 16 + (lane >> 2), col0 = wn * 64 + (lane & 3) * 2;
        #pragma unroll
        for (int nt = 0; nt < 8; nt++) {
            *(float2*)&stg[r * 132 + col0 + nt * 8]       = make_float2(c[nt][0], c[nt][1]);
            *(float2*)&stg[(r + 8) * 132 + col0 + nt * 8] = make_float2(c[nt][2], c[nt][3]);
        }
    }
    __syncthreads();

    if constexpr (MODE == 3) {
        int r = tid >> 2, qd = tid & 3;
        #pragma unroll
        for (int j = 0; j < 8; j++) {
            float4 v = *(float4*)&stg[r * 132 + qd * 32 + j * 4];
            *(float4*)(dstf + (size_t)(m0 + r) * 512 + n0 + qd * 32 + j * 4) = v;
        }
    } else if constexpr (MODE == 2) {
        #pragma unroll
        for (int i = 0; i < 4; i++) {            // V -> [hb][dk][l]
            int e = tid + 256 * i;
            int s = e >> 9, rem = e & 511, dk = rem >> 3, lc = rem & 7;
            int hb = (2 * ny + s) * 4 + bI;
            float v[8];
            #pragma unroll
            for (int kk = 0; kk < 8; kk++) v[kk] = stg[(lc * 8 + kk) * 132 + s * 64 + dk];
            uint4 hi, lo; pack8(v, hi, lo);
            size_t ui = (size_t)(hb * 64 + dk) * 128 + l0 / 8 + lc;
            ((uint4*)g_vhi)[ui] = hi;
            ((uint4*)g_vlo)[ui] = lo;
        }
    } else {
        uint4* dhi = (uint4*)(MODE ? g_khi : g_qhi);
        uint4* dlo = (uint4*)(MODE ? g_klo : g_qlo);
        #pragma unroll
        for (int i = 0; i < 4; i++) {            // Q/K -> [hb][l][dk]
            int e = tid + 256 * i;
            int s = e >> 9, rem = e & 511, row = rem >> 3, q = rem & 7;
            int hb = (2 * ny + s) * 4 + bI;
            float v[8];
            #pragma unroll
            for (int kk = 0; kk < 8; kk++) v[kk] = stg[row * 132 + s * 64 + q * 8 + kk];
            uint4 hi, lo; pack8(v, hi, lo);
            size_t ui = (size_t)(hb * 1024 + l0 + row) * 8 + q;
            dhi[ui] = hi;
            dlo[ui] = lo;
        }
    }
}

// ---------------- scores: QK^T -> unnormalized exp (bf16 pair) + rowsums -----
#define SC_QHI 0
#define SC_QLO 18432
#define SC_KHI 36864
#define SC_KLO 55296
#define SC_STH 73728
#define SC_STL 110592
#define SC_RS  147456
#define SC_SZ  147968
__global__ __launch_bounds__(256, 1)
void scores_mma() {
    extern __shared__ char sm[];
    const uint32_t sb = smem_u32(sm);
    uint16_t* stgH = (uint16_t*)(sm + SC_STH);   // [128][144]
    uint16_t* stgL = (uint16_t*)(sm + SC_STL);
    float* rsm = (float*)(sm + SC_RS);
    const int tid = threadIdx.x, wid = tid >> 5, lane = tid & 31;
    const int hb = blockIdx.y, r0 = blockIdx.x * 128;

    #pragma unroll
    for (int i = 0; i < 4; i++) {
        int e = tid + 256 * i, row = e >> 3, q = e & 7;
        uint32_t off = (uint32_t)row * ROWB + q * 16;
        size_t gi = (size_t)(hb * 1024 + r0 + row) * 8 + q;
        *(uint4*)(sm + SC_QHI + off) = ((const uint4*)g_qhi)[gi];
        *(uint4*)(sm + SC_QLO + off) = ((const uint4*)g_qlo)[gi];
    }
    __syncthreads();
    uint32_t ah[4][4], al[4][4];
    load_afrags(sb + SC_QHI, wid * 16, lane, ah);
    load_afrags(sb + SC_QLO, wid * 16, lane, al);

    float rs0 = 0.f, rs1 = 0.f;

    for (int ck = 0; ck < 8; ck++) {
        __syncthreads();
        #pragma unroll
        for (int i = 0; i < 4; i++) {
            int e = tid + 256 * i, row = e >> 3, q = e & 7;
            uint32_t off = (uint32_t)row * ROWB + q * 16;
            size_t gi = (size_t)(hb * 1024 + ck * 128 + row) * 8 + q;
            *(uint4*)(sm + SC_KHI + off) = ((const uint4*)g_khi)[gi];
            *(uint4*)(sm + SC_KLO + off) = ((const uint4*)g_klo)[gi];
        }
        __syncthreads();
        int r = wid * 16 + (lane >> 2), col0 = (lane & 3) * 2;
        #pragma unroll
        for (int nt = 0; nt < 16; nt++) {
            float c[4] = {0.f, 0.f, 0.f, 0.f};
            uint32_t rb = sb + SC_KHI + (uint32_t)(nt * 8 + (lane & 7)) * ROWB
                        + (((lane >> 3) & 1) << 4);
            #pragma unroll
            for (int ks = 0; ks < 4; ks++) {
                uint32_t bh0, bh1, bl0, bl1;
                ldsm2(bh0, bh1, rb + ks * 32);
                ldsm2(bl0, bl1, rb + (SC_KLO - SC_KHI) + ks * 32);
                mma_bf16(c, ah[ks], bh0, bh1);
                mma_bf16(c, ah[ks], bl0, bl1);
                mma_bf16(c, al[ks], bh0, bh1);
            }
            float e0 = __expf(0.125f * c[0]), e1 = __expf(0.125f * c[1]);
            float e2 = __expf(0.125f * c[2]), e3 = __expf(0.125f * c[3]);
            rs0 += e0 + e1; rs1 += e2 + e3;
            *(uint32_t*)&stgH[r * 144 + nt * 8 + col0]       = bfpair_hi(e0, e1);
            *(uint32_t*)&stgL[r * 144 + nt * 8 + col0]       = bfpair_lo(e0, e1);
            *(uint32_t*)&stgH[(r + 8) * 144 + nt * 8 + col0] = bfpair_hi(e2, e3);
            *(uint32_t*)&stgL[(r + 8) * 144 + nt * 8 + col0] = bfpair_lo(e2, e3);
        }
        __syncthreads();
        int rr = tid >> 1, half = tid & 1;
        size_t dbase = (size_t)(hb * 1024 + r0 + rr) * 128 + ck * 16 + half * 8;
        const uint4* sh4 = (const uint4*)(sm + SC_STH) + rr * 18 + half * 8;
        const uint4* sl4 = (const uint4*)(sm + SC_STL) + rr * 18 + half * 8;
        #pragma unroll
        for (int j = 0; j < 8; j++) {
            ((uint4*)g_ehi)[dbase + j] = sh4[j];
            ((uint4*)g_elo)[dbase + j] = sl4[j];
        }
    }
    rs0 += __shfl_xor_sync(0xffffffffu, rs0, 1); rs0 += __shfl_xor_sync(0xffffffffu, rs0, 2);
    rs1 += __shfl_xor_sync(0xffffffffu, rs1, 1); rs1 += __shfl_xor_sync(0xffffffffu, rs1, 2);
    if ((lane & 3) == 0) {
        rsm[wid * 16 + (lane >> 2)]     = rs0;
        rsm[wid * 16 + (lane >> 2) + 8] = rs1;
    }
    __syncthreads();
    if (tid < 128) g_R[hb * 1024 + r0 + tid] = rsm[tid];
}

// ---------------- pv: O = (E @ V)/rowsum ; also emits normalized series ------
#define PV_AHI 0
#define PV_ALO 18432
#define PV_BHI 36864
#define PV_BLO 46080
#define PV_ST  55296
#define PV_SZ  90112
__global__ __launch_bounds__(256, 2)
void pv_mma(float* __restrict__ series) {
    extern __shared__ char sm[];
    const uint32_t sb = smem_u32(sm);
    float* stg = (float*)(sm + PV_ST);           // [128][68]
    const int tid = threadIdx.x, wid = tid >> 5, lane = tid & 31;
    const int hb = blockIdx.y, r0 = blockIdx.x * 128;

    float c[8][4];
    #pragma unroll
    for (int t2 = 0; t2 < 8; t2++) { c[t2][0]=c[t2][1]=c[t2][2]=c[t2][3]=0.f; }

    for (int kc = 0; kc < 16; kc++) {
        __syncthreads();
        #pragma unroll
        for (int i = 0; i < 4; i++) {            // E tiles + series write
            int e = tid + 256 * i, row = e >> 3, q = e & 7;
            size_t gi = (size_t)(hb * 1024 + r0 + row) * 128 + kc * 8 + q;
            uint4 h4 = ((const uint4*)g_ehi)[gi];
            uint4 l4 = ((const uint4*)g_elo)[gi];
            uint32_t off = (uint32_t)row * ROWB + q * 16;
            *(uint4*)(sm + PV_AHI + off) = h4;
            *(uint4*)(sm + PV_ALO + off) = l4;
            float ri = 1.0f / g_R[hb * 1024 + r0 + row];
            float4 s0 = make_float4((bhi(h4.x << 16) + bhi(l4.x << 16)) * ri,
                                    (bhi(h4.x) + bhi(l4.x)) * ri,
                                    (bhi(h4.y << 16) + bhi(l4.y << 16)) * ri,
                                    (bhi(h4.y) + bhi(l4.y)) * ri);
            float4 s1 = make_float4((bhi(h4.z << 16) + bhi(l4.z << 16)) * ri,
                                    (bhi(h4.z) + bhi(l4.z)) * ri,
                                    (bhi(h4.w << 16) + bhi(l4.w << 16)) * ri,
                                    (bhi(h4.w) + bhi(l4.w)) * ri);
            float* sp = series + (size_t)(hb * 1024 + r0 + row) * 1024 + kc * 64 + q * 8;
            *(float4*)sp = s0;
            *(float4*)(sp + 4) = s1;
        }
        #pragma unroll
        for (int i = 0; i < 2; i++) {            // V tiles
            int e = tid + 256 * i, row = e >> 3, q = e & 7;
            uint32_t off = (uint32_t)row * ROWB + q * 16;
            size_t gi = (size_t)(hb * 64 + row) * 128 + kc * 8 + q;
            *(uint4*)(sm + PV_BHI + off) = ((const uint4*)g_vhi)[gi];
            *(uint4*)(sm + PV_BLO + off) = ((const uint4*)g_vlo)[gi];
        }
        __syncthreads();
        uint32_t ah[4][4], al[4][4];
        load_afrags(sb + PV_AHI, wid * 16, lane, ah);
        load_afrags(sb + PV_ALO, wid * 16, lane, al);
        #pragma unroll
        for (int nt = 0; nt < 8; nt++) {
            uint32_t rb = sb + PV_BHI + (uint32_t)(nt * 8 + (lane & 7)) * ROWB
                        + (((lane >> 3) & 1) << 4);
            #pragma unroll
            for (int ks = 0; ks < 4; ks++) {
                uint32_t bh0, bh1, bl0, bl1;
                ldsm2(bh0, bh1, rb + ks * 32);
                ldsm2(bl0, bl1, rb + (PV_BLO - PV_BHI) + ks * 32);
                mma_bf16(c[nt], ah[ks], bh0, bh1);
                mma_bf16(c[nt], ah[ks], bl0, bl1);
                mma_bf16(c[nt], al[ks], bh0, bh1);
            }
        }
    }
    // scale by 1/rowsum, stage, store
    float rv0 = 1.0f / g_R[hb * 1024 + r0 + wid * 16 + (lane >> 2)];
    float rv1 = 1.0f / g_R[hb * 1024 + r0 + wid * 16 + (lane >> 2) + 8];
    __syncthreads();
    {
        int r = wid * 16 + (lane >> 2), col0 = (lane & 3) * 2;
        #pragma unroll
        for (int nt = 0; nt < 8; nt++) {
            *(float2*)&stg[r * 68 + nt * 8 + col0]       = make_float2(c[nt][0]*rv0, c[nt][1]*rv0);
            *(float2*)&stg[(r + 8) * 68 + nt * 8 + col0] = make_float2(c[nt][2]*rv1, c[nt][3]*rv1);
        }
    }
    __syncthreads();
    const int h = hb >> 2, b = hb & 3;
    int r = tid >> 1, ch = (tid & 1) * 32;
    #pragma unroll
    for (int j = 0; j < 8; j++) {
        float4 v = *(float4*)&stg[r * 68 + ch + j * 4];
        *(float4*)(g_om + (size_t)(b * 1024 + r0 + r) * 512 + h * 64 + ch + j * 4) = v;
    }
}

// ---------------- launcher ---------------------------------------------------
extern "C" void kernel_launch(void* const* d_in, const int* in_sizes, int n_in,
                              void* d_out, int out_size) {
    const float* Sigma = (const float*)d_in[0];
    const float* Q     = (const float*)d_in[1];
    const float* K     = (const float*)d_in[2];
    const float* V     = (const float*)d_in[3];
    const float* Ws    = (const float*)d_in[4];
    const float* Wq    = (const float*)d_in[5];
    const float* Wk    = (const float*)d_in[6];
    const float* Wv    = (const float*)d_in[7];
    const float* Wo    = (const float*)d_in[8];

    float* out    = (float*)d_out;
    float* prior  = out;
    float* series = out + 33554432;
    float* final_ = out + 67108864;

    static bool attr_done = false;
    if (!attr_done) {
        cudaFuncSetAttribute(proj_mma<0>, cudaFuncAttributeMaxDynamicSharedMemorySize, PJ_SZ);
        cudaFuncSetAttribute(proj_mma<1>, cudaFuncAttributeMaxDynamicSharedMemorySize, PJ_SZ);
        cudaFuncSetAttribute(proj_mma<2>, cudaFuncAttributeMaxDynamicSharedMemorySize, PJ_SZ);
        cudaFuncSetAttribute(proj_mma<3>, cudaFuncAttributeMaxDynamicSharedMemorySize, PJ_SZ);
        cudaFuncSetAttribute(scores_mma,  cudaFuncAttributeMaxDynamicSharedMemorySize, SC_SZ);
        cudaFuncSetAttribute(pv_mma,      cudaFuncAttributeMaxDynamicSharedMemorySize, PV_SZ);
        attr_done = true;
    }

    wsplit<<<1024, 256>>>(Wq, Wk, Wv, Wo);
    sigma_proj<<<32, 128>>>(Sigma, Ws);

    dim3 gpj(64, 4);
    proj_mma<0><<<gpj, 256, PJ_SZ>>>(Q, nullptr);
    proj_mma<1><<<gpj, 256, PJ_SZ>>>(K, nullptr);
    proj_mma<2><<<gpj, 256, PJ_SZ>>>(V, nullptr);

    prior_kernel<<<dim3(1024, 32), 256>>>(prior);

    scores_mma<<<dim3(8, 32), 256, SC_SZ>>>();
    pv_mma<<<dim3(8, 32), 256, PV_SZ>>>(series);

    proj_mma<3><<<gpj, 256, PJ_SZ>>>(nullptr, final_);
}